// round 16
// baseline (speedup 1.0000x reference)
#include <cuda_runtime.h>
#include <cuda_bf16.h>
#include <stdint.h>

// Problem constants
#define BATCH   4
#define TSEQ    4096
#define DEMB    512
#define DH      64
#define NTOK    (BATCH * TSEQ)   // 16384

// ---------------------------------------------------------------------------
// Global scratch.  Q is stored PRE-SCALED by log2(e) (hi/lo bf16 split).
// ---------------------------------------------------------------------------
__device__ __nv_bfloat16 g_Qh[NTOK * DH];
__device__ __nv_bfloat16 g_Ql[NTOK * DH];
__device__ __nv_bfloat16 g_Kh[NTOK * DH];
__device__ __nv_bfloat16 g_Kl[NTOK * DH];
__device__ __nv_bfloat16 g_Vh[NTOK * DH];
__device__ __nv_bfloat16 g_Vl[NTOK * DH];

// Pre-split weights: rows 0-63 = Wq, 64-127 = Wk, 128-191 = Wv ([192][512])
__device__ __nv_bfloat16 g_Wsh[192 * DEMB];
__device__ __nv_bfloat16 g_Wsl[192 * DEMB];

// Split-KV partials (fixed-base => combine is a pure sum).
// slot = ((b*64 + qt)*4 + chunk); only qt>=16 groups use partials.
#define NSLOT (BATCH * 64 * 4)
__device__ float g_pO[NSLOT * 64 * 64];
__device__ float g_pl[NSLOT * 64];

// ---------------------------------------------------------------------------
// Helpers
// ---------------------------------------------------------------------------
__device__ __forceinline__ uint32_t smem_u32(const void* p) {
    uint32_t a;
    asm("{ .reg .u64 t; cvta.to.shared.u64 t, %1; cvt.u32.u64 %0, t; }"
        : "=r"(a) : "l"(p));
    return a;
}

#define SWZ(o) ((o) ^ (((o) >> 3) & 0x70))

#define LDSM_X4(r, addr) \
    asm volatile("ldmatrix.sync.aligned.m8n8.x4.shared.b16 {%0,%1,%2,%3}, [%4];" \
        : "=r"((r)[0]), "=r"((r)[1]), "=r"((r)[2]), "=r"((r)[3]) : "r"(addr))
#define LDSM_X4_T(r, addr) \
    asm volatile("ldmatrix.sync.aligned.m8n8.x4.trans.shared.b16 {%0,%1,%2,%3}, [%4];" \
        : "=r"((r)[0]), "=r"((r)[1]), "=r"((r)[2]), "=r"((r)[3]) : "r"(addr))

#define CP_ASYNC16(dst, src) \
    asm volatile("cp.async.cg.shared.global [%0], [%1], 16;" \
        :: "r"(dst), "l"(src))
#define CP_COMMIT()  asm volatile("cp.async.commit_group;" ::: "memory")
#define CP_WAIT(n)   asm volatile("cp.async.wait_group %0;" :: "n"(n) : "memory")

// m16n8k16 bf16 -> f32 accumulate (HMMA)
__device__ __forceinline__ void mma_bf16(float* c, const uint32_t* a, const uint32_t* b) {
    asm volatile(
        "mma.sync.aligned.m16n8k16.row.col.f32.bf16.bf16.f32 "
        "{%0,%1,%2,%3}, {%4,%5,%6,%7}, {%8,%9}, {%0,%1,%2,%3};"
        : "+f"(c[0]), "+f"(c[1]), "+f"(c[2]), "+f"(c[3])
        : "r"(a[0]), "r"(a[1]), "r"(a[2]), "r"(a[3]), "r"(b[0]), "r"(b[1]));
}

#define L2E   1.44269504088896f
// fixed softmax base: exp(s - 32)  ->  exp2(s*L2E - 32*L2E)
#define SBASE 46.1662413081947f

// MUFU exp2 (single-instruction; saturates to 0 for very negative args)
__device__ __forceinline__ float ex2(float x) {
    float y;
    asm("ex2.approx.f32 %0, %1;" : "=f"(y) : "f"(x));
    return y;
}

__device__ __forceinline__ void split_bf16(float v, unsigned short& h, unsigned short& l) {
    __nv_bfloat16 hb = __float2bfloat16(v);
    float hf = __bfloat162float(hb);
    __nv_bfloat16 lb = __float2bfloat16(v - hf);
    h = __bfloat16_as_ushort(hb);
    l = __bfloat16_as_ushort(lb);
}

__device__ __forceinline__ void pack4(const float4 v, uint2& h, uint2& l) {
    unsigned short h0, l0, h1, l1, h2, l2, h3, l3;
    split_bf16(v.x, h0, l0); split_bf16(v.y, h1, l1);
    split_bf16(v.z, h2, l2); split_bf16(v.w, h3, l3);
    h = make_uint2((uint32_t)h0 | ((uint32_t)h1 << 16),
                   (uint32_t)h2 | ((uint32_t)h3 << 16));
    l = make_uint2((uint32_t)l0 | ((uint32_t)l1 << 16),
                   (uint32_t)l2 | ((uint32_t)l3 << 16));
}

// ---------------------------------------------------------------------------
// Kernel 0: pre-split weights into bf16 hi/lo (float4 per thread).
// ---------------------------------------------------------------------------
__global__ __launch_bounds__(256) void wsplit_kernel(
    const float* __restrict__ Wq, const float* __restrict__ Wk,
    const float* __restrict__ Wv)
{
    int idx4 = blockIdx.x * 256 + threadIdx.x;     // 0 .. 24575
    int row  = idx4 >> 7;                          // 0..191
    int col  = (idx4 & 127) * 4;
    const float* W = (row < 64) ? Wq : (row < 128) ? Wk : Wv;
    int r = row & 63;
    float4 v = *(const float4*)(W + (size_t)r * DEMB + col);
    uint2 h, l;
    pack4(v, h, l);
    *(uint2*)(g_Wsh + (size_t)row * DEMB + col) = h;
    *(uint2*)(g_Wsl + (size_t)row * DEMB + col) = l;
}

// ---------------------------------------------------------------------------
// Kernel 1: fused QKV projection via HMMA. One CTA = 64 tokens x ALL 192
// outputs. 256 threads = 8 warps in a 4(M) x 2(N) grid.
// Q outputs (and bias) pre-scaled by log2(e).   (round-14 proven version)
// ---------------------------------------------------------------------------
#define QF_XH 0
#define QF_XL 8192
#define QF_WH 16384
#define QF_WL 40960
#define QF_SMEM 65536

__global__ __launch_bounds__(256) void qkv_fused_kernel(
    const float* __restrict__ X,
    const float* __restrict__ bq, const float* __restrict__ bk,
    const float* __restrict__ bv)
{
    extern __shared__ char smc[];
    const uint32_t smb = smem_u32(smc);

    const int m0   = blockIdx.x * 64;
    const int tid  = threadIdx.x;
    const int w    = tid >> 5;
    const int lane = tid & 31;
    const int g    = lane >> 2;
    const int tq   = lane & 3;
    const int mh   = w >> 1;      // 0..3 : 16-row slice
    const int nh   = w & 1;       // 0..1 : 96-col slice

    float c[12][4];
    #pragma unroll
    for (int nb = 0; nb < 12; nb++)
        #pragma unroll
        for (int e = 0; e < 4; e++) c[nb][e] = 0.f;

    const int arow  = 16 * mh + (lane & 15);
    const int kh8   = (lane >> 4) & 1;
    const int krow  = (lane & 7) + 8 * ((lane >> 4) & 1);
    const int kbyte = ((lane >> 3) & 1) * 16;

    for (int kc = 0; kc < 8; kc++) {
        __syncthreads();   // prev compute done before overwriting tiles

        // Prefetch W tiles [192][64] bf16 h/l via cp.async
        #pragma unroll
        for (int it = 0; it < 6; it++) {
            int e   = tid + it * 256;        // 0..1535
            int row = e >> 3;
            int c8  = e & 7;
            uint32_t dsto = SWZ((uint32_t)(row * 128 + 16 * c8));
            const char* srch = (const char*)(g_Wsh + (size_t)row * DEMB + kc * 64 + 8 * c8);
            const char* srcl = (const char*)(g_Wsl + (size_t)row * DEMB + kc * 64 + 8 * c8);
            CP_ASYNC16(smb + QF_WH + dsto, srch);
            CP_ASYNC16(smb + QF_WL + dsto, srcl);
        }
        CP_COMMIT();

        // Load + split X tile [64 tok][64 k]
        #pragma unroll
        for (int it = 0; it < 4; it++) {
            int e   = tid + it * 256;        // 0..1023 float4
            int row = e >> 4;
            int c4  = e & 15;
            float4 xv = *(const float4*)(X + (size_t)(m0 + row) * DEMB + kc * 64 + 4 * c4);
            uint2 h, l;
            pack4(xv, h, l);
            uint32_t bo = SWZ((uint32_t)(row * 128 + 8 * c4));
            *(uint2*)(smc + QF_XH + bo) = h;
            *(uint2*)(smc + QF_XL + bo) = l;
        }
        CP_WAIT(0);
        __syncthreads();

        uint32_t ah[4][4], al[4][4];
        #pragma unroll
        for (int s = 0; s < 4; s++) {
            uint32_t off = SWZ((uint32_t)(arow * 128 + s * 32 + kh8 * 16));
            LDSM_X4(ah[s], smb + QF_XH + off);
            LDSM_X4(al[s], smb + QF_XL + off);
        }
        #pragma unroll
        for (int jp = 0; jp < 6; jp++) {
            #pragma unroll
            for (int s = 0; s < 4; s++) {
                uint32_t off = SWZ((uint32_t)((96 * nh + 16 * jp + krow) * 128 + s * 32 + kbyte));
                uint32_t bh[4], bl[4];
                LDSM_X4(bh, smb + QF_WH + off);
                LDSM_X4(bl, smb + QF_WL + off);
                mma_bf16(c[2 * jp],     ah[s], bh);
                mma_bf16(c[2 * jp],     al[s], bh);
                mma_bf16(c[2 * jp],     ah[s], bl);
                mma_bf16(c[2 * jp + 1], ah[s], bh + 2);
                mma_bf16(c[2 * jp + 1], al[s], bh + 2);
                mma_bf16(c[2 * jp + 1], ah[s], bl + 2);
            }
        }
    }

    // Epilogue (Q channel scaled by log2(e))
    const int r0 = m0 + 16 * mh + g;
    const int r1 = r0 + 8;
    #pragma unroll
    for (int nb = 0; nb < 12; nb++) {
        int gcol  = 96 * nh + 8 * nb + 2 * tq;   // 0..191
        int which = gcol >> 6;
        int col   = gcol & 63;
        const float* bias = (which == 0) ? bq : (which == 1) ? bk : bv;
        __nv_bfloat16* Ch = (which == 0) ? g_Qh : (which == 1) ? g_Kh : g_Vh;
        __nv_bfloat16* Cl = (which == 0) ? g_Ql : (which == 1) ? g_Kl : g_Vl;
        float sc = (which == 0) ? L2E : 1.0f;
        float b0 = bias[col], b1 = bias[col + 1];
        unsigned short h0, l0, h1, l1;
        split_bf16((c[nb][0] + b0) * sc, h0, l0);
        split_bf16((c[nb][1] + b1) * sc, h1, l1);
        *(uint32_t*)(Ch + (size_t)r0 * DH + col) = (uint32_t)h0 | ((uint32_t)h1 << 16);
        *(uint32_t*)(Cl + (size_t)r0 * DH + col) = (uint32_t)l0 | ((uint32_t)l1 << 16);
        split_bf16((c[nb][2] + b0) * sc, h0, l0);
        split_bf16((c[nb][3] + b1) * sc, h1, l1);
        *(uint32_t*)(Ch + (size_t)r1 * DH + col) = (uint32_t)h0 | ((uint32_t)h1 << 16);
        *(uint32_t*)(Cl + (size_t)r1 * DH + col) = (uint32_t)l0 | ((uint32_t)l1 << 16);
    }
}

// ---------------------------------------------------------------------------
// Kernel 2: split-KV causal HMMA flash attention, fixed-base softmax.
// 3-stage cp.async ring, ONE __syncthreads per iteration.
// exp on MUFU (ex2.approx); row-sums l accumulated on the TENSOR pipe via
// an extra MMA against a ones fragment (no scalar adds, no final shuffles).
// qt<16 (single chunk): write Out directly. qt>=16: plain-sum partials.
// 2 CTAs/SM (register-file bound; 3 CTAs spills — verified rounds 6 & 9).
// ---------------------------------------------------------------------------
#define SMEM_ATTN (3 * 32768)   // 98304

__global__ __launch_bounds__(128, 2) void attn_part_kernel(float* __restrict__ Out)
{
    extern __shared__ char smc[];
    const uint32_t smb = smem_u32(smc);

    const int tid  = threadIdx.x;
    const int w    = tid >> 5;
    const int lane = tid & 31;
    const int g    = lane >> 2;
    const int tq   = lane & 3;

    // blockIdx -> (b, qt, chunk); qt descending within each segment
    const int id = blockIdx.x;
    const int b  = id / 160;
    const int r  = id % 160;
    int qt, ch;
    if      (r <  64) { qt = 63 - r;          ch = 0; }
    else if (r < 112) { qt = 63 - (r - 64);   ch = 1; }   // 63..16
    else if (r < 144) { qt = 63 - (r - 112);  ch = 2; }   // 63..32
    else              { qt = 63 - (r - 144);  ch = 3; }   // 63..48
    const int k_lo = 16 * ch;
    const int k_hi = min(qt, 16 * ch + 15);
    const int slot = (b * 64 + qt) * 4 + ch;
    const int q0   = qt * 64;

    // ---- stage Q through stage-0 smem, extract fragments ----
    {
        const uint4* sqh = (const uint4*)(g_Qh + ((size_t)b * TSEQ + q0) * DH);
        const uint4* sql = (const uint4*)(g_Ql + ((size_t)b * TSEQ + q0) * DH);
        #pragma unroll
        for (int t = 0; t < 4; t++) {
            int e = tid + t * 128;
            uint32_t bo = SWZ((uint32_t)e * 16);
            *(uint4*)(smc + bo)        = sqh[e];
            *(uint4*)(smc + 8192 + bo) = sql[e];
        }
    }
    __syncthreads();

    uint32_t qh[4][4], ql[4][4];
    {
        int arow = 16 * w + (lane & 15);
        int kh8  = (lane >> 4) & 1;
        #pragma unroll
        for (int s = 0; s < 4; s++) {
            uint32_t off = SWZ((uint32_t)(arow * 128 + s * 32 + kh8 * 16));
            LDSM_X4(qh[s], smb + off);
            LDSM_X4(ql[s], smb + 8192 + off);
        }
    }
    __syncthreads();   // all warps done reading Q before stage 0 is reused

    // prefetch: KV tile kt (clamped) -> stage st
    auto prefetch = [&](int kt, int st) {
        const int k0 = min(kt, 63) * 64;
        const uint32_t base = smb + st * 32768;
        const char* srck_h = (const char*)(g_Kh + ((size_t)b * TSEQ + k0) * DH);
        const char* srck_l = (const char*)(g_Kl + ((size_t)b * TSEQ + k0) * DH);
        const char* srcv_h = (const char*)(g_Vh + ((size_t)b * TSEQ + k0) * DH);
        const char* srcv_l = (const char*)(g_Vl + ((size_t)b * TSEQ + k0) * DH);
        #pragma unroll
        for (int t = 0; t < 4; t++) {
            int e = tid + t * 128;              // 0..511 (16B units)
            uint32_t bo = SWZ((uint32_t)e * 16);
            CP_ASYNC16(base         + bo, srck_h + e * 16);
            CP_ASYNC16(base + 8192  + bo, srck_l + e * 16);
            CP_ASYNC16(base + 16384 + bo, srcv_h + e * 16);
            CP_ASYNC16(base + 24576 + bo, srcv_l + e * 16);
        }
    };

    // prologue: stages 0 and 1 (second may be an empty group)
    prefetch(k_lo, 0);
    CP_COMMIT();
    if (k_lo + 1 <= k_hi) prefetch(k_lo + 1, 1);
    CP_COMMIT();

    float O[8][4];
    #pragma unroll
    for (int n = 0; n < 8; n++)
        #pragma unroll
        for (int e = 0; e < 4; e++) O[n][e] = 0.f;
    float Cl[4] = {0.f, 0.f, 0.f, 0.f};     // l row-sums via tensor pipe
    const uint32_t bones[2] = {0x3F803F80u, 0x3F803F80u};  // bf16 ones

    const int krow  = (lane & 7) + 8 * ((lane >> 4) & 1);
    const int kbyte = ((lane >> 3) & 1) * 16;
    const int vrow4 = (lane & 7) + 8 * ((lane >> 3) & 1);
    const int vcol4 = (lane >> 4) & 1;

    int st = 0;
    for (int kt = k_lo; kt <= k_hi; kt++) {
        CP_WAIT(1);          // group for kt complete (<=1 pending: kt+1's)
        __syncthreads();     // all threads' kt data visible; all done with kt-1

        // prefetch kt+2 into stage of kt-1 (safe: everyone passed the barrier)
        if (kt + 2 <= k_hi) prefetch(kt + 2, (st + 2) % 3);
        CP_COMMIT();

        const uint32_t KH = smb + st * 32768;
        const uint32_t KL = KH + 8192;
        const uint32_t VH = KH + 16384;
        const uint32_t VL = KH + 24576;

        // ---- S = Q K^T - SBASE (bias folded into accumulator init) ----
        float C[8][4];
        #pragma unroll
        for (int j = 0; j < 8; j++)
            #pragma unroll
            for (int e = 0; e < 4; e++) C[j][e] = -SBASE;

        #pragma unroll
        for (int jp = 0; jp < 4; jp++) {
            #pragma unroll
            for (int s = 0; s < 4; s++) {
                uint32_t off = SWZ((uint32_t)((16 * jp + krow) * 128 + s * 32 + kbyte));
                uint32_t bh[4], bl[4];
                LDSM_X4(bh, KH + off);
                LDSM_X4(bl, KL + off);
                mma_bf16(C[2 * jp],     qh[s], bh);
                mma_bf16(C[2 * jp],     ql[s], bh);
                mma_bf16(C[2 * jp],     qh[s], bl);
                mma_bf16(C[2 * jp + 1], qh[s], bh + 2);
                mma_bf16(C[2 * jp + 1], ql[s], bh + 2);
                mma_bf16(C[2 * jp + 1], qh[s], bl + 2);
            }
        }

        // ---- causal mask (diagonal tile only) ----
        if (kt == qt) {
            int r0l = 16 * w + g;
            int r1l = r0l + 8;
            #pragma unroll
            for (int j = 0; j < 8; j++) {
                int col = 8 * j + 2 * tq;
                if (col     > r0l) C[j][0] = -1e30f;
                if (col + 1 > r0l) C[j][1] = -1e30f;
                if (col     > r1l) C[j][2] = -1e30f;
                if (col + 1 > r1l) C[j][3] = -1e30f;
            }
        }

        // ---- fixed-base softmax: p = ex2(C) on the MUFU pipe ----
        uint32_t ph[4][4], pl[4][4];
        #pragma unroll
        for (int j = 0; j < 8; j++) {
            float p00 = ex2(C[j][0]);
            float p01 = ex2(C[j][1]);
            float p10 = ex2(C[j][2]);
            float p11 = ex2(C[j][3]);

            __nv_bfloat162 H0 = __floats2bfloat162_rn(p00, p01);
            __nv_bfloat162 H1 = __floats2bfloat162_rn(p10, p11);
            __nv_bfloat162 L0 = __floats2bfloat162_rn(p00 - __bfloat162float(H0.x),
                                                      p01 - __bfloat162float(H0.y));
            __nv_bfloat162 L1 = __floats2bfloat162_rn(p10 - __bfloat162float(H1.x),
                                                      p11 - __bfloat162float(H1.y));
            int sp  = j >> 1;
            int rlo = (j & 1) * 2;
            ph[sp][rlo]     = *(uint32_t*)&H0;
            ph[sp][rlo + 1] = *(uint32_t*)&H1;
            pl[sp][rlo]     = *(uint32_t*)&L0;
            pl[sp][rlo + 1] = *(uint32_t*)&L1;
        }

        // ---- l += P @ ones  (tensor pipe, replaces 32 scalar adds) ----
        #pragma unroll
        for (int s = 0; s < 4; s++) {
            mma_bf16(Cl, ph[s], bones);
            mma_bf16(Cl, pl[s], bones);
        }

        // ---- O += P V (V row-major, X4 trans loads) ----
        #pragma unroll
        for (int np = 0; np < 4; np++) {
            #pragma unroll
            for (int s = 0; s < 4; s++) {
                uint32_t off = SWZ((uint32_t)((16 * s + vrow4) * 128 + (2 * np + vcol4) * 16));
                uint32_t vh[4], vl[4];
                LDSM_X4_T(vh, VH + off);
                LDSM_X4_T(vl, VL + off);
                mma_bf16(O[2 * np],     ph[s], vh);
                mma_bf16(O[2 * np],     pl[s], vh);
                mma_bf16(O[2 * np],     ph[s], vl);
                mma_bf16(O[2 * np + 1], ph[s], vh + 2);
                mma_bf16(O[2 * np + 1], pl[s], vh + 2);
                mma_bf16(O[2 * np + 1], ph[s], vl + 2);
            }
        }

        st = (st + 1) % 3;
        // no trailing barrier: next iteration's top barrier provides it
    }

    // l for this thread's two rows comes straight out of the MMA accumulator
    const float s0acc = Cl[0];
    const float s1acc = Cl[2];

    const int r0l = 16 * w + g;
    const int r1l = r0l + 8;

    if (qt < 16) {
        // single chunk: write final output directly
        float inv0 = 8.0f / s0acc, inv1 = 8.0f / s1acc;
        float* dst = Out + ((size_t)b * TSEQ + q0) * DH;
        #pragma unroll
        for (int n = 0; n < 8; n++) {
            int col = 8 * n + 2 * tq;
            *(float2*)(dst + (size_t)r0l * DH + col) =
                make_float2(O[n][0] * inv0, O[n][1] * inv0);
            *(float2*)(dst + (size_t)r1l * DH + col) =
                make_float2(O[n][2] * inv1, O[n][3] * inv1);
        }
    } else {
        float* pO = g_pO + (size_t)slot * 64 * 64;
        #pragma unroll
        for (int n = 0; n < 8; n++) {
            int col = 8 * n + 2 * tq;
            *(float2*)(pO + r0l * 64 + col) = make_float2(O[n][0], O[n][1]);
            *(float2*)(pO + r1l * 64 + col) = make_float2(O[n][2], O[n][3]);
        }
        if (tq == 0) {
            g_pl[slot * 64 + r0l] = s0acc;
            g_pl[slot * 64 + r1l] = s1acc;
        }
    }
}

// ---------------------------------------------------------------------------
// Kernel 3: combine = sum partials + normalize, qt >= 16 only.
// One thread per HALF-ROW (8 float4s) for MLP ~8: 24576 threads.
// ---------------------------------------------------------------------------
__global__ __launch_bounds__(256) void attn_combine_kernel(float* __restrict__ Out)
{
    const int t    = blockIdx.x * 256 + threadIdx.x;   // 0..24575
    const int hf   = t & 1;               // half-row
    const int rowg = t >> 1;              // 0..12287
    const int b    = rowg / 3072;
    const int qt   = 16 + ((rowg % 3072) >> 6);
    const int row  = rowg & 63;

    const int nc    = (qt >> 4) + 1;      // 2..4
    const int sbase = (b * 64 + qt) * 4;
    const int coff  = row * 64 + hf * 32; // float offset within 64x64 tile

    float l = 0.f;
    float4 acc[8];
    #pragma unroll
    for (int j = 0; j < 8; j++) acc[j] = make_float4(0.f, 0.f, 0.f, 0.f);

    for (int c = 0; c < nc; c++) {
        l += g_pl[(sbase + c) * 64 + row];
        const float4* src = (const float4*)(g_pO + (size_t)(sbase + c) * 4096 + coff);
        #pragma unroll
        for (int j = 0; j < 8; j++) {
            float4 v = src[j];
            acc[j].x += v.x; acc[j].y += v.y; acc[j].z += v.z; acc[j].w += v.w;
        }
    }
    float inv = 8.0f / l;
    float4* dst = (float4*)(Out + ((size_t)b * TSEQ + (size_t)qt * 64 + row) * DH + hf * 32);
    #pragma unroll
    for (int j = 0; j < 8; j++)
        dst[j] = make_float4(acc[j].x * inv, acc[j].y * inv,
                             acc[j].z * inv, acc[j].w * inv);
}

// ---------------------------------------------------------------------------
// Launch: inputs per metadata order: x, Wq_w, Wq_b, Wk_w, Wk_b, Wv_w, Wv_b
// ---------------------------------------------------------------------------
extern "C" void kernel_launch(void* const* d_in, const int* in_sizes, int n_in,
                              void* d_out, int out_size)
{
    const float* x  = (const float*)d_in[0];
    const float* Wq = (const float*)d_in[1];
    const float* bq = (const float*)d_in[2];
    const float* Wk = (const float*)d_in[3];
    const float* bk = (const float*)d_in[4];
    const float* Wv = (const float*)d_in[5];
    const float* bv = (const float*)d_in[6];
    float* out = (float*)d_out;

    wsplit_kernel<<<96, 256>>>(Wq, Wk, Wv);

    cudaFuncSetAttribute(qkv_fused_kernel,
                         cudaFuncAttributeMaxDynamicSharedMemorySize,
                         QF_SMEM);
    qkv_fused_kernel<<<256, 256, QF_SMEM>>>(x, bq, bk, bv);

    cudaFuncSetAttribute(attn_part_kernel,
                         cudaFuncAttributeMaxDynamicSharedMemorySize,
                         SMEM_ATTN);
    attn_part_kernel<<<640, 128, SMEM_ATTN>>>(out);

    attn_combine_kernel<<<96, 256>>>(out);
}

// round 17
// speedup vs baseline: 1.0366x; 1.0366x over previous
#include <cuda_runtime.h>
#include <cuda_bf16.h>
#include <stdint.h>

// Problem constants
#define BATCH   4
#define TSEQ    4096
#define DEMB    512
#define DH      64
#define NTOK    (BATCH * TSEQ)   // 16384

// ---------------------------------------------------------------------------
// Global scratch.  Q is stored PRE-SCALED by log2(e) (hi/lo bf16 split).
// ---------------------------------------------------------------------------
__device__ __nv_bfloat16 g_Qh[NTOK * DH];
__device__ __nv_bfloat16 g_Ql[NTOK * DH];
__device__ __nv_bfloat16 g_Kh[NTOK * DH];
__device__ __nv_bfloat16 g_Kl[NTOK * DH];
__device__ __nv_bfloat16 g_Vh[NTOK * DH];
__device__ __nv_bfloat16 g_Vl[NTOK * DH];

// Pre-split weights: rows 0-63 = Wq, 64-127 = Wk, 128-191 = Wv ([192][512])
__device__ __nv_bfloat16 g_Wsh[192 * DEMB];
__device__ __nv_bfloat16 g_Wsl[192 * DEMB];

// Split-KV partials (fixed-base => combine is a pure sum).
// slot = ((b*64 + qt)*4 + chunk); only qt>=16 groups use partials.
#define NSLOT (BATCH * 64 * 4)
__device__ float g_pO[NSLOT * 64 * 64];
__device__ float g_pl[NSLOT * 64];

// ---------------------------------------------------------------------------
// Helpers
// ---------------------------------------------------------------------------
__device__ __forceinline__ uint32_t smem_u32(const void* p) {
    uint32_t a;
    asm("{ .reg .u64 t; cvta.to.shared.u64 t, %1; cvt.u32.u64 %0, t; }"
        : "=r"(a) : "l"(p));
    return a;
}

#define SWZ(o) ((o) ^ (((o) >> 3) & 0x70))

#define LDSM_X4(r, addr) \
    asm volatile("ldmatrix.sync.aligned.m8n8.x4.shared.b16 {%0,%1,%2,%3}, [%4];" \
        : "=r"((r)[0]), "=r"((r)[1]), "=r"((r)[2]), "=r"((r)[3]) : "r"(addr))
#define LDSM_X4_T(r, addr) \
    asm volatile("ldmatrix.sync.aligned.m8n8.x4.trans.shared.b16 {%0,%1,%2,%3}, [%4];" \
        : "=r"((r)[0]), "=r"((r)[1]), "=r"((r)[2]), "=r"((r)[3]) : "r"(addr))

#define CP_ASYNC16(dst, src) \
    asm volatile("cp.async.cg.shared.global [%0], [%1], 16;" \
        :: "r"(dst), "l"(src))
#define CP_COMMIT()  asm volatile("cp.async.commit_group;" ::: "memory")
#define CP_WAIT(n)   asm volatile("cp.async.wait_group %0;" :: "n"(n) : "memory")

// m16n8k16 bf16 -> f32 accumulate (HMMA)
__device__ __forceinline__ void mma_bf16(float* c, const uint32_t* a, const uint32_t* b) {
    asm volatile(
        "mma.sync.aligned.m16n8k16.row.col.f32.bf16.bf16.f32 "
        "{%0,%1,%2,%3}, {%4,%5,%6,%7}, {%8,%9}, {%0,%1,%2,%3};"
        : "+f"(c[0]), "+f"(c[1]), "+f"(c[2]), "+f"(c[3])
        : "r"(a[0]), "r"(a[1]), "r"(a[2]), "r"(a[3]), "r"(b[0]), "r"(b[1]));
}

#define L2E   1.44269504088896f
// fixed softmax base: exp(s - 32)  ->  exp2(s*L2E - 32*L2E)
#define SBASE 46.1662413081947f

// MUFU exp2 (single-instruction; saturates to 0 for very negative args)
__device__ __forceinline__ float ex2(float x) {
    float y;
    asm("ex2.approx.f32 %0, %1;" : "=f"(y) : "f"(x));
    return y;
}

__device__ __forceinline__ void split_bf16(float v, unsigned short& h, unsigned short& l) {
    __nv_bfloat16 hb = __float2bfloat16(v);
    float hf = __bfloat162float(hb);
    __nv_bfloat16 lb = __float2bfloat16(v - hf);
    h = __bfloat16_as_ushort(hb);
    l = __bfloat16_as_ushort(lb);
}

__device__ __forceinline__ void pack4(const float4 v, uint2& h, uint2& l) {
    unsigned short h0, l0, h1, l1, h2, l2, h3, l3;
    split_bf16(v.x, h0, l0); split_bf16(v.y, h1, l1);
    split_bf16(v.z, h2, l2); split_bf16(v.w, h3, l3);
    h = make_uint2((uint32_t)h0 | ((uint32_t)h1 << 16),
                   (uint32_t)h2 | ((uint32_t)h3 << 16));
    l = make_uint2((uint32_t)l0 | ((uint32_t)l1 << 16),
                   (uint32_t)l2 | ((uint32_t)l3 << 16));
}

// ---------------------------------------------------------------------------
// Kernel 0: pre-split weights into bf16 hi/lo (float4 per thread).
// ---------------------------------------------------------------------------
__global__ __launch_bounds__(256) void wsplit_kernel(
    const float* __restrict__ Wq, const float* __restrict__ Wk,
    const float* __restrict__ Wv)
{
    int idx4 = blockIdx.x * 256 + threadIdx.x;     // 0 .. 24575
    int row  = idx4 >> 7;                          // 0..191
    int col  = (idx4 & 127) * 4;
    const float* W = (row < 64) ? Wq : (row < 128) ? Wk : Wv;
    int r = row & 63;
    float4 v = *(const float4*)(W + (size_t)r * DEMB + col);
    uint2 h, l;
    pack4(v, h, l);
    *(uint2*)(g_Wsh + (size_t)row * DEMB + col) = h;
    *(uint2*)(g_Wsl + (size_t)row * DEMB + col) = l;
}

// ---------------------------------------------------------------------------
// Kernel 1: fused QKV projection via HMMA. One CTA = 64 tokens x ALL 192
// outputs. 256 threads = 8 warps in a 4(M) x 2(N) grid.
// Q outputs (and bias) pre-scaled by log2(e).   (round-14 proven version)
// ---------------------------------------------------------------------------
#define QF_XH 0
#define QF_XL 8192
#define QF_WH 16384
#define QF_WL 40960
#define QF_SMEM 65536

__global__ __launch_bounds__(256) void qkv_fused_kernel(
    const float* __restrict__ X,
    const float* __restrict__ bq, const float* __restrict__ bk,
    const float* __restrict__ bv)
{
    extern __shared__ char smc[];
    const uint32_t smb = smem_u32(smc);

    const int m0   = blockIdx.x * 64;
    const int tid  = threadIdx.x;
    const int w    = tid >> 5;
    const int lane = tid & 31;
    const int g    = lane >> 2;
    const int tq   = lane & 3;
    const int mh   = w >> 1;      // 0..3 : 16-row slice
    const int nh   = w & 1;       // 0..1 : 96-col slice

    float c[12][4];
    #pragma unroll
    for (int nb = 0; nb < 12; nb++)
        #pragma unroll
        for (int e = 0; e < 4; e++) c[nb][e] = 0.f;

    const int arow  = 16 * mh + (lane & 15);
    const int kh8   = (lane >> 4) & 1;
    const int krow  = (lane & 7) + 8 * ((lane >> 4) & 1);
    const int kbyte = ((lane >> 3) & 1) * 16;

    for (int kc = 0; kc < 8; kc++) {
        __syncthreads();   // prev compute done before overwriting tiles

        // Prefetch W tiles [192][64] bf16 h/l via cp.async
        #pragma unroll
        for (int it = 0; it < 6; it++) {
            int e   = tid + it * 256;        // 0..1535
            int row = e >> 3;
            int c8  = e & 7;
            uint32_t dsto = SWZ((uint32_t)(row * 128 + 16 * c8));
            const char* srch = (const char*)(g_Wsh + (size_t)row * DEMB + kc * 64 + 8 * c8);
            const char* srcl = (const char*)(g_Wsl + (size_t)row * DEMB + kc * 64 + 8 * c8);
            CP_ASYNC16(smb + QF_WH + dsto, srch);
            CP_ASYNC16(smb + QF_WL + dsto, srcl);
        }
        CP_COMMIT();

        // Load + split X tile [64 tok][64 k]
        #pragma unroll
        for (int it = 0; it < 4; it++) {
            int e   = tid + it * 256;        // 0..1023 float4
            int row = e >> 4;
            int c4  = e & 15;
            float4 xv = *(const float4*)(X + (size_t)(m0 + row) * DEMB + kc * 64 + 4 * c4);
            uint2 h, l;
            pack4(xv, h, l);
            uint32_t bo = SWZ((uint32_t)(row * 128 + 8 * c4));
            *(uint2*)(smc + QF_XH + bo) = h;
            *(uint2*)(smc + QF_XL + bo) = l;
        }
        CP_WAIT(0);
        __syncthreads();

        uint32_t ah[4][4], al[4][4];
        #pragma unroll
        for (int s = 0; s < 4; s++) {
            uint32_t off = SWZ((uint32_t)(arow * 128 + s * 32 + kh8 * 16));
            LDSM_X4(ah[s], smb + QF_XH + off);
            LDSM_X4(al[s], smb + QF_XL + off);
        }
        #pragma unroll
        for (int jp = 0; jp < 6; jp++) {
            #pragma unroll
            for (int s = 0; s < 4; s++) {
                uint32_t off = SWZ((uint32_t)((96 * nh + 16 * jp + krow) * 128 + s * 32 + kbyte));
                uint32_t bh[4], bl[4];
                LDSM_X4(bh, smb + QF_WH + off);
                LDSM_X4(bl, smb + QF_WL + off);
                mma_bf16(c[2 * jp],     ah[s], bh);
                mma_bf16(c[2 * jp],     al[s], bh);
                mma_bf16(c[2 * jp],     ah[s], bl);
                mma_bf16(c[2 * jp + 1], ah[s], bh + 2);
                mma_bf16(c[2 * jp + 1], al[s], bh + 2);
                mma_bf16(c[2 * jp + 1], ah[s], bl + 2);
            }
        }
    }

    // Epilogue (Q channel scaled by log2(e))
    const int r0 = m0 + 16 * mh + g;
    const int r1 = r0 + 8;
    #pragma unroll
    for (int nb = 0; nb < 12; nb++) {
        int gcol  = 96 * nh + 8 * nb + 2 * tq;   // 0..191
        int which = gcol >> 6;
        int col   = gcol & 63;
        const float* bias = (which == 0) ? bq : (which == 1) ? bk : bv;
        __nv_bfloat16* Ch = (which == 0) ? g_Qh : (which == 1) ? g_Kh : g_Vh;
        __nv_bfloat16* Cl = (which == 0) ? g_Ql : (which == 1) ? g_Kl : g_Vl;
        float sc = (which == 0) ? L2E : 1.0f;
        float b0 = bias[col], b1 = bias[col + 1];
        unsigned short h0, l0, h1, l1;
        split_bf16((c[nb][0] + b0) * sc, h0, l0);
        split_bf16((c[nb][1] + b1) * sc, h1, l1);
        *(uint32_t*)(Ch + (size_t)r0 * DH + col) = (uint32_t)h0 | ((uint32_t)h1 << 16);
        *(uint32_t*)(Cl + (size_t)r0 * DH + col) = (uint32_t)l0 | ((uint32_t)l1 << 16);
        split_bf16((c[nb][2] + b0) * sc, h0, l0);
        split_bf16((c[nb][3] + b1) * sc, h1, l1);
        *(uint32_t*)(Ch + (size_t)r1 * DH + col) = (uint32_t)h0 | ((uint32_t)h1 << 16);
        *(uint32_t*)(Cl + (size_t)r1 * DH + col) = (uint32_t)l0 | ((uint32_t)l1 << 16);
    }
}

// ---------------------------------------------------------------------------
// Kernel 2: split-KV causal HMMA flash attention, fixed-base softmax.
// 3-stage cp.async ring, ONE __syncthreads per iteration.
// Prologue overlaps Q gmem loads with KV prefetch: K/V for the first two
// iterations go into stages 1 and 2 FIRST; Q stages through stage-0 smem,
// which the loop first overwrites only after the barrier that follows the
// Q-fragment extraction.
// exp on MUFU (ex2.approx); row-sums l accumulated on the TENSOR pipe.
// qt<16 (single chunk): write Out directly. qt>=16: plain-sum partials.
// 2 CTAs/SM (register-file bound; 3 CTAs spills — verified rounds 6 & 9).
// ---------------------------------------------------------------------------
#define SMEM_ATTN (3 * 32768)   // 98304

__global__ __launch_bounds__(128, 2) void attn_part_kernel(float* __restrict__ Out)
{
    extern __shared__ char smc[];
    const uint32_t smb = smem_u32(smc);

    const int tid  = threadIdx.x;
    const int w    = tid >> 5;
    const int lane = tid & 31;
    const int g    = lane >> 2;
    const int tq   = lane & 3;

    // blockIdx -> (b, qt, chunk); qt descending within each segment
    const int id = blockIdx.x;
    const int b  = id / 160;
    const int r  = id % 160;
    int qt, ch;
    if      (r <  64) { qt = 63 - r;          ch = 0; }
    else if (r < 112) { qt = 63 - (r - 64);   ch = 1; }   // 63..16
    else if (r < 144) { qt = 63 - (r - 112);  ch = 2; }   // 63..32
    else              { qt = 63 - (r - 144);  ch = 3; }   // 63..48
    const int k_lo = 16 * ch;
    const int k_hi = min(qt, 16 * ch + 15);
    const int slot = (b * 64 + qt) * 4 + ch;
    const int q0   = qt * 64;

    // prefetch: KV tile kt (clamped) -> stage st
    auto prefetch = [&](int kt, int st) {
        const int k0 = min(kt, 63) * 64;
        const uint32_t base = smb + st * 32768;
        const char* srck_h = (const char*)(g_Kh + ((size_t)b * TSEQ + k0) * DH);
        const char* srck_l = (const char*)(g_Kl + ((size_t)b * TSEQ + k0) * DH);
        const char* srcv_h = (const char*)(g_Vh + ((size_t)b * TSEQ + k0) * DH);
        const char* srcv_l = (const char*)(g_Vl + ((size_t)b * TSEQ + k0) * DH);
        #pragma unroll
        for (int t = 0; t < 4; t++) {
            int e = tid + t * 128;              // 0..511 (16B units)
            uint32_t bo = SWZ((uint32_t)e * 16);
            CP_ASYNC16(base         + bo, srck_h + e * 16);
            CP_ASYNC16(base + 8192  + bo, srck_l + e * 16);
            CP_ASYNC16(base + 16384 + bo, srcv_h + e * 16);
            CP_ASYNC16(base + 24576 + bo, srcv_l + e * 16);
        }
    };

    // ---- KV prefetch for first two iterations FIRST (stages 1, 2) ----
    prefetch(k_lo, 1);
    CP_COMMIT();
    if (k_lo + 1 <= k_hi) prefetch(k_lo + 1, 2);
    CP_COMMIT();

    // ---- stage Q through stage-0 smem (overlaps with KV prefetch) ----
    {
        const uint4* sqh = (const uint4*)(g_Qh + ((size_t)b * TSEQ + q0) * DH);
        const uint4* sql = (const uint4*)(g_Ql + ((size_t)b * TSEQ + q0) * DH);
        #pragma unroll
        for (int t = 0; t < 4; t++) {
            int e = tid + t * 128;
            uint32_t bo = SWZ((uint32_t)e * 16);
            *(uint4*)(smc + bo)        = sqh[e];
            *(uint4*)(smc + 8192 + bo) = sql[e];
        }
    }
    __syncthreads();

    uint32_t qh[4][4], ql[4][4];
    {
        int arow = 16 * w + (lane & 15);
        int kh8  = (lane >> 4) & 1;
        #pragma unroll
        for (int s = 0; s < 4; s++) {
            uint32_t off = SWZ((uint32_t)(arow * 128 + s * 32 + kh8 * 16));
            LDSM_X4(qh[s], smb + off);
            LDSM_X4(ql[s], smb + 8192 + off);
        }
    }
    __syncthreads();   // all warps done reading Q before stage 0 is reused

    float O[8][4];
    #pragma unroll
    for (int n = 0; n < 8; n++)
        #pragma unroll
        for (int e = 0; e < 4; e++) O[n][e] = 0.f;
    float Cl[4] = {0.f, 0.f, 0.f, 0.f};     // l row-sums via tensor pipe
    const uint32_t bones[2] = {0x3F803F80u, 0x3F803F80u};  // bf16 ones

    const int krow  = (lane & 7) + 8 * ((lane >> 4) & 1);
    const int kbyte = ((lane >> 3) & 1) * 16;
    const int vrow4 = (lane & 7) + 8 * ((lane >> 3) & 1);
    const int vcol4 = (lane >> 4) & 1;

    int st = 1;   // first KV tile is in stage 1
    for (int kt = k_lo; kt <= k_hi; kt++) {
        CP_WAIT(1);          // group for kt complete (<=1 pending: kt+1's)
        __syncthreads();     // all threads' kt data visible; all done with kt-1

        // prefetch kt+2 into stage (st+2)%3 (first reuse of stage 0 is here,
        // ordered after the Q-fragment extraction barrier above)
        if (kt + 2 <= k_hi) prefetch(kt + 2, (st + 2) % 3);
        CP_COMMIT();

        const uint32_t KH = smb + st * 32768;
        const uint32_t KL = KH + 8192;
        const uint32_t VH = KH + 16384;
        const uint32_t VL = KH + 24576;

        // ---- S = Q K^T - SBASE (bias folded into accumulator init) ----
        float C[8][4];
        #pragma unroll
        for (int j = 0; j < 8; j++)
            #pragma unroll
            for (int e = 0; e < 4; e++) C[j][e] = -SBASE;

        #pragma unroll
        for (int jp = 0; jp < 4; jp++) {
            #pragma unroll
            for (int s = 0; s < 4; s++) {
                uint32_t off = SWZ((uint32_t)((16 * jp + krow) * 128 + s * 32 + kbyte));
                uint32_t bh[4], bl[4];
                LDSM_X4(bh, KH + off);
                LDSM_X4(bl, KL + off);
                mma_bf16(C[2 * jp],     qh[s], bh);
                mma_bf16(C[2 * jp],     ql[s], bh);
                mma_bf16(C[2 * jp],     qh[s], bl);
                mma_bf16(C[2 * jp + 1], qh[s], bh + 2);
                mma_bf16(C[2 * jp + 1], ql[s], bh + 2);
                mma_bf16(C[2 * jp + 1], qh[s], bl + 2);
            }
        }

        // ---- causal mask (diagonal tile only) ----
        if (kt == qt) {
            int r0l = 16 * w + g;
            int r1l = r0l + 8;
            #pragma unroll
            for (int j = 0; j < 8; j++) {
                int col = 8 * j + 2 * tq;
                if (col     > r0l) C[j][0] = -1e30f;
                if (col + 1 > r0l) C[j][1] = -1e30f;
                if (col     > r1l) C[j][2] = -1e30f;
                if (col + 1 > r1l) C[j][3] = -1e30f;
            }
        }

        // ---- fixed-base softmax: p = ex2(C) on the MUFU pipe ----
        uint32_t ph[4][4], pl[4][4];
        #pragma unroll
        for (int j = 0; j < 8; j++) {
            float p00 = ex2(C[j][0]);
            float p01 = ex2(C[j][1]);
            float p10 = ex2(C[j][2]);
            float p11 = ex2(C[j][3]);

            __nv_bfloat162 H0 = __floats2bfloat162_rn(p00, p01);
            __nv_bfloat162 H1 = __floats2bfloat162_rn(p10, p11);
            __nv_bfloat162 L0 = __floats2bfloat162_rn(p00 - __bfloat162float(H0.x),
                                                      p01 - __bfloat162float(H0.y));
            __nv_bfloat162 L1 = __floats2bfloat162_rn(p10 - __bfloat162float(H1.x),
                                                      p11 - __bfloat162float(H1.y));
            int sp  = j >> 1;
            int rlo = (j & 1) * 2;
            ph[sp][rlo]     = *(uint32_t*)&H0;
            ph[sp][rlo + 1] = *(uint32_t*)&H1;
            pl[sp][rlo]     = *(uint32_t*)&L0;
            pl[sp][rlo + 1] = *(uint32_t*)&L1;
        }

        // ---- l += P @ ones  (tensor pipe, replaces 32 scalar adds) ----
        #pragma unroll
        for (int s = 0; s < 4; s++) {
            mma_bf16(Cl, ph[s], bones);
            mma_bf16(Cl, pl[s], bones);
        }

        // ---- O += P V (V row-major, X4 trans loads) ----
        #pragma unroll
        for (int np = 0; np < 4; np++) {
            #pragma unroll
            for (int s = 0; s < 4; s++) {
                uint32_t off = SWZ((uint32_t)((16 * s + vrow4) * 128 + (2 * np + vcol4) * 16));
                uint32_t vh[4], vl[4];
                LDSM_X4_T(vh, VH + off);
                LDSM_X4_T(vl, VL + off);
                mma_bf16(O[2 * np],     ph[s], vh);
                mma_bf16(O[2 * np],     pl[s], vh);
                mma_bf16(O[2 * np],     ph[s], vl);
                mma_bf16(O[2 * np + 1], ph[s], vh + 2);
                mma_bf16(O[2 * np + 1], pl[s], vh + 2);
                mma_bf16(O[2 * np + 1], ph[s], vl + 2);
            }
        }

        st = (st + 1) % 3;
        // no trailing barrier: next iteration's top barrier provides it
    }

    // l for this thread's two rows comes straight out of the MMA accumulator
    const float s0acc = Cl[0];
    const float s1acc = Cl[2];

    const int r0l = 16 * w + g;
    const int r1l = r0l + 8;

    if (qt < 16) {
        // single chunk: write final output directly
        float inv0 = 8.0f / s0acc, inv1 = 8.0f / s1acc;
        float* dst = Out + ((size_t)b * TSEQ + q0) * DH;
        #pragma unroll
        for (int n = 0; n < 8; n++) {
            int col = 8 * n + 2 * tq;
            *(float2*)(dst + (size_t)r0l * DH + col) =
                make_float2(O[n][0] * inv0, O[n][1] * inv0);
            *(float2*)(dst + (size_t)r1l * DH + col) =
                make_float2(O[n][2] * inv1, O[n][3] * inv1);
        }
    } else {
        float* pO = g_pO + (size_t)slot * 64 * 64;
        #pragma unroll
        for (int n = 0; n < 8; n++) {
            int col = 8 * n + 2 * tq;
            *(float2*)(pO + r0l * 64 + col) = make_float2(O[n][0], O[n][1]);
            *(float2*)(pO + r1l * 64 + col) = make_float2(O[n][2], O[n][3]);
        }
        if (tq == 0) {
            g_pl[slot * 64 + r0l] = s0acc;
            g_pl[slot * 64 + r1l] = s1acc;
        }
    }
}

// ---------------------------------------------------------------------------
// Kernel 3: combine = sum partials + normalize, qt >= 16 only.
// One thread per output float4 (round-14 proven version): 196608 threads.
// ---------------------------------------------------------------------------
__global__ __launch_bounds__(256) void attn_combine_kernel(float* __restrict__ Out)
{
    const int t    = blockIdx.x * 256 + threadIdx.x;   // 0..196607
    const int f4   = t & 15;
    const int rowg = t >> 4;              // 0..12287
    const int b    = rowg / 3072;
    const int qt   = 16 + ((rowg % 3072) >> 6);
    const int row  = rowg & 63;

    const int nc    = (qt >> 4) + 1;      // 2..4
    const int sbase = (b * 64 + qt) * 4;

    float l = 0.f;
    float4 acc = make_float4(0.f, 0.f, 0.f, 0.f);
    #pragma unroll 4
    for (int c = 0; c < nc; c++) {
        l += g_pl[(sbase + c) * 64 + row];
        const float4 v = *(const float4*)(g_pO + (size_t)(sbase + c) * 4096 + row * 64 + 4 * f4);
        acc.x += v.x; acc.y += v.y; acc.z += v.z; acc.w += v.w;
    }
    float inv = 8.0f / l;
    *(float4*)(Out + ((size_t)b * TSEQ + (size_t)qt * 64 + row) * DH + 4 * f4) =
        make_float4(acc.x * inv, acc.y * inv, acc.z * inv, acc.w * inv);
}

// ---------------------------------------------------------------------------
// Launch: inputs per metadata order: x, Wq_w, Wq_b, Wk_w, Wk_b, Wv_w, Wv_b
// ---------------------------------------------------------------------------
extern "C" void kernel_launch(void* const* d_in, const int* in_sizes, int n_in,
                              void* d_out, int out_size)
{
    const float* x  = (const float*)d_in[0];
    const float* Wq = (const float*)d_in[1];
    const float* bq = (const float*)d_in[2];
    const float* Wk = (const float*)d_in[3];
    const float* bk = (const float*)d_in[4];
    const float* Wv = (const float*)d_in[5];
    const float* bv = (const float*)d_in[6];
    float* out = (float*)d_out;

    wsplit_kernel<<<96, 256>>>(Wq, Wk, Wv);

    cudaFuncSetAttribute(qkv_fused_kernel,
                         cudaFuncAttributeMaxDynamicSharedMemorySize,
                         QF_SMEM);
    qkv_fused_kernel<<<256, 256, QF_SMEM>>>(x, bq, bk, bv);

    cudaFuncSetAttribute(attn_part_kernel,
                         cudaFuncAttributeMaxDynamicSharedMemorySize,
                         SMEM_ATTN);
    attn_part_kernel<<<640, 128, SMEM_ATTN>>>(out);

    attn_combine_kernel<<<768, 256>>>(out);
}